// round 11
// baseline (speedup 1.0000x reference)
#include <cuda_runtime.h>
#include <cuda_fp16.h>
#include <math.h>

// ---------------------------------------------------------------------------
// MotionOptimalTransportLoss — GB300 sm_103a
// fp16 mma.sync m16n8k16 (tcgen05 NOT available on this build path:
// harness emits compute_103 PTX and ptxas rejects arch-specific instrs).
// style: 128x64 CTA tiles, 32x32 warp tiles, 3 CTAs/SM.
// cov:   64x64 channel tiles. Both: 3-stage cp.async ring, batched LDSM.
// ---------------------------------------------------------------------------

#define NPAD 1024
#define SCRPB 983040   // (64+128+256+512)*1024

__device__ __half    g_scm[2u * 8u * SCRPB];   // channel-major [c][1024]
__device__ __half    g_spm[2u * 8u * SCRPB];   // point-major  [1024][c]
__device__ float     g_nsq[2 * 32 * 1024];
__device__ float     g_musum[2 * 32 * 512];
__device__ unsigned  g_rmin[32 * 1024];
__device__ unsigned  g_cmin[32 * 1024];
__device__ float     g_cov[32];
__device__ float     g_pl[32];

__constant__ int OFFC[4] = {0, 65536, 196608, 458752};

__device__ __forceinline__ unsigned f2o(float f) {
    unsigned u = __float_as_uint(f);
    return (u & 0x80000000u) ? ~u : (u | 0x80000000u);
}
__device__ __forceinline__ float o2f(unsigned u) {
    return __uint_as_float((u & 0x80000000u) ? (u ^ 0x80000000u) : ~u);
}
__device__ __forceinline__ void hmma16(float* d, const unsigned* a, const unsigned* b) {
    asm volatile(
        "mma.sync.aligned.m16n8k16.row.col.f32.f16.f16.f32 "
        "{%0,%1,%2,%3}, {%4,%5,%6,%7}, {%8,%9}, {%0,%1,%2,%3};\n"
        : "+f"(d[0]), "+f"(d[1]), "+f"(d[2]), "+f"(d[3])
        : "r"(a[0]), "r"(a[1]), "r"(a[2]), "r"(a[3]), "r"(b[0]), "r"(b[1]));
}
__device__ __forceinline__ void ldsm4(unsigned& r0, unsigned& r1, unsigned& r2,
                                      unsigned& r3, const void* p) {
    unsigned addr = (unsigned)__cvta_generic_to_shared(p);
    asm volatile("ldmatrix.sync.aligned.m8n8.x4.shared.b16 {%0,%1,%2,%3}, [%4];"
                 : "=r"(r0), "=r"(r1), "=r"(r2), "=r"(r3) : "r"(addr));
}
__device__ __forceinline__ void cp16(void* dst, const void* src) {
    unsigned d = (unsigned)__cvta_generic_to_shared(dst);
    asm volatile("cp.async.cg.shared.global [%0], [%1], 16;\n" :: "r"(d), "l"(src));
}
__device__ __forceinline__ void cp_commit() { asm volatile("cp.async.commit_group;\n"); }
__device__ __forceinline__ void cp_wait1()  { asm volatile("cp.async.wait_group 1;\n"); }
__device__ __forceinline__ void cp_wait0()  { asm volatile("cp.async.wait_group 0;\n"); }

// ---------------------------------------------------------------------------
__global__ void k_init_a() {
    int i = blockIdx.x * blockDim.x + threadIdx.x;
    if (i < 32768) { g_rmin[i] = 0xFF800000u; g_cmin[i] = 0xFF800000u; }
}
__global__ void k_init_b() {
    int i = blockIdx.x * blockDim.x + threadIdx.x;
    if (i < 65536) g_nsq[i] = 0.f;
    if (i < 32768) g_musum[i] = 0.f;
    if (i < 32) g_cov[i] = 0.f;
}

// ---------------------------------------------------------------------------
// gather2: fused gather + nsq + channel sums + dual-layout write.
// ---------------------------------------------------------------------------
__global__ void k_gather2(const float* __restrict__ tf0, const float* __restrict__ gf0,
                          const float* __restrict__ tf1, const float* __restrict__ gf1,
                          const float* __restrict__ tf2, const float* __restrict__ gf2,
                          const float* __restrict__ tf3, const float* __restrict__ gf3,
                          const int* __restrict__ ix0, const int* __restrict__ ix1,
                          const int* __restrict__ ix2) {
    __shared__ __half tl[64][72];

    int gblk = blockIdx.x;
    int tb = gblk / 240;
    int t2 = tb >> 3, b = tb & 7;
    int r = gblk % 240;
    int lv = 0;
    { const int sz[4] = {16, 32, 64, 128};
      while (r >= sz[lv]) { r -= sz[lv]; lv++; } }
    int C = 64 << lv;
    int ch0 = (r >> 4) * 64, n0 = (r & 15) * 64;
    int hw = 65536 >> (2 * lv);
    int N = (lv == 3) ? 1024 : 1000;

    const float* feat; const int* idx;
    switch (lv) {
        case 0: feat = t2 ? gf0 : tf0; idx = ix0; break;
        case 1: feat = t2 ? gf1 : tf1; idx = ix1; break;
        case 2: feat = t2 ? gf2 : tf2; idx = ix2; break;
        default: feat = t2 ? gf3 : tf3; idx = 0; break;
    }

    int tid = threadIdx.x;
    int nl = tid & 63;
    int n = n0 + nl;
    int chg = tid >> 6;
    bool valid = (n < N);
    int src = 0;
    if (valid) src = idx ? idx[b * 1000 + n] : n;

    size_t fb = ((size_t)b * C + ch0) * hw + src;
    __half* cm = g_scm + ((size_t)t2 * 8 + b) * SCRPB + OFFC[lv];
    float nsq_loc = 0.f;
#pragma unroll
    for (int k = 0; k < 16; k++) {
        int chl = chg * 16 + k;
        float v = valid ? feat[fb + (size_t)chl * hw] : 0.f;
        nsq_loc += v * v;
        __half h = __float2half_rn(v);
        cm[(size_t)(ch0 + chl) * NPAD + n] = h;
        tl[chl][nl] = h;
    }
    int pairbase = (t2 * 32 + b * 4 + lv) * 1024;
    atomicAdd(&g_nsq[pairbase + n], nsq_loc);
    __syncthreads();

    __half* pm = g_spm + ((size_t)t2 * 8 + b) * SCRPB + OFFC[lv];
    int row = tid >> 2, q = tid & 3;
#pragma unroll
    for (int j = 0; j < 8; j++) {
        int cc = q * 16 + 2 * j;
        __half2 w = __halves2half2(tl[cc][row], tl[cc + 1][row]);
        *(__half2*)&pm[(size_t)(n0 + row) * C + ch0 + cc] = w;
    }

    {
        int ch = tid >> 2;
        float s = 0.f;
#pragma unroll
        for (int i2 = 0; i2 < 16; i2++) s += __half2float(tl[ch][q * 16 + i2]);
        s += __shfl_xor_sync(0xFFFFFFFFu, s, 1);
        s += __shfl_xor_sync(0xFFFFFFFFu, s, 2);
        if (q == 0)
            atomicAdd(&g_musum[(t2 * 32 + b * 4 + lv) * 512 + ch0 + ch], s);
    }
}

// ---------------------------------------------------------------------------
// k_main: cov + style. grid (562, 8): bx<50 cov, else style (lv descending).
// ---------------------------------------------------------------------------
#define CS 72
#define CSTGB (2 * 64 * CS * 2)    // 18432 B per cov stage
#define PS 40                       // style smem row stride (halves)
#define SSTGB ((128 + 64) * PS * 2) // 15360 B per style stage (A+B)
#define DSMB (3 * CSTGB)            // 55296

extern __shared__ char dsm[];

__device__ __forceinline__ void cov_body(int bx, int b, unsigned* s_aux) {
    float* red = (float*)s_aux;
    int lv = 0;
    { const int TRI[4] = {1, 3, 10, 36};
      while (bx >= TRI[lv]) { bx -= TRI[lv]; lv++; } }
    int T = 1 << lv;
    int ta = 0, rem = bx;
    while (rem >= T - ta) { rem -= (T - ta); ta++; }
    int tb = ta + rem;

    int off = OFFC[lv];
    int N = (lv == 3) ? 1024 : 1000;
    int tid = threadIdx.x, wid = tid >> 5, lane = tid & 31;
    int g = lane >> 2, t = lane & 3;
    int grp = lane >> 3;
    int wm = (wid >> 2) * 32, wn = (wid & 3) * 16;
    int cha0 = ta * 64, chb0 = tb * 64;
    const __half* X = g_scm + (size_t)b * SCRPB + off;
    const __half* Y = g_scm + (size_t)(8 + b) * SCRPB + off;

    float acc[2][2][2][4];
#pragma unroll
    for (int p = 0; p < 2; p++)
#pragma unroll
        for (int mt = 0; mt < 2; mt++)
#pragma unroll
            for (int nt = 0; nt < 2; nt++)
#pragma unroll
                for (int rr = 0; rr < 4; rr++) acc[p][mt][nt][rr] = 0.f;

    int lrow = tid >> 2, lq = tid & 3;

#define COV_ISSUE(IT) do {                                                     \
        int p_ = (IT) >> 4, n1_ = ((IT) & 15) * 64;                            \
        const __half* s_ = p_ ? Y : X;                                         \
        __half* A_ = (__half*)(dsm + ((IT) % 3) * CSTGB);                      \
        __half* B_ = A_ + 64 * CS;                                             \
        _Pragma("unroll")                                                      \
        for (int j = 0; j < 2; j++) {                                          \
            int col = lq * 16 + j * 8;                                         \
            cp16(&A_[lrow * CS + col], &s_[(size_t)(cha0 + lrow) * NPAD + n1_ + col]); \
            cp16(&B_[lrow * CS + col], &s_[(size_t)(chb0 + lrow) * NPAD + n1_ + col]); \
        }                                                                      \
        cp_commit();                                                           \
    } while (0)

    COV_ISSUE(0);
    COV_ISSUE(1);
    for (int it = 0; it < 32; it++) {
        if (it + 1 < 32) cp_wait1(); else cp_wait0();
        __syncthreads();
        if (it + 2 < 32) COV_ISSUE(it + 2);

        int p = it >> 4;
        const __half* As = (const __half*)(dsm + (it % 3) * CSTGB);
        const __half* Bsm = As + 64 * CS;
        // two pairs of k16 steps; batch LDSM ahead of HMMA within each pair
#pragma unroll
        for (int hp = 0; hp < 2; hp++) {
            unsigned a[2][2][4], bb[2][2][2];
#pragma unroll
            for (int s2 = 0; s2 < 2; s2++) {
                int k16 = (hp * 2 + s2) * 16;
#pragma unroll
                for (int mt = 0; mt < 2; mt++) {
                    int ar = wm + mt * 16 + (lane & 15);
                    ldsm4(a[s2][mt][0], a[s2][mt][1], a[s2][mt][2], a[s2][mt][3],
                          &As[ar * CS + k16 + ((lane >> 4) << 3)]);
                }
                int br = wn + (grp >> 1) * 8 + (lane & 7);
                ldsm4(bb[s2][0][0], bb[s2][0][1], bb[s2][1][0], bb[s2][1][1],
                      &Bsm[br * CS + k16 + ((grp & 1) << 3)]);
            }
#pragma unroll
            for (int s2 = 0; s2 < 2; s2++)
#pragma unroll
                for (int mt = 0; mt < 2; mt++)
#pragma unroll
                    for (int nt = 0; nt < 2; nt++)
                        hmma16(acc[p][mt][nt], a[s2][mt], bb[s2][nt]);
        }
    }
#undef COV_ISSUE

    int pair = b * 4 + lv;
    const float* sux = g_musum + pair * 512;
    const float* suy = g_musum + (32 + pair) * 512;
    float Nf = (float)N, inv_nm1 = 1.f / (Nf - 1.f), invN = 1.f / Nf;
    float local = 0.f;
#pragma unroll
    for (int mt = 0; mt < 2; mt++)
#pragma unroll
        for (int h = 0; h < 2; h++) {
            int row = cha0 + wm + mt * 16 + g + h * 8;
            float sxa = sux[row], sya = suy[row];
#pragma unroll
            for (int nt = 0; nt < 2; nt++)
#pragma unroll
                for (int u = 0; u < 2; u++) {
                    int col = chb0 + wn + nt * 8 + 2 * t + u;
                    float corr = (sxa * sux[col] - sya * suy[col]) * invN;
                    float cd = (acc[0][mt][nt][h * 2 + u] - acc[1][mt][nt][h * 2 + u]
                                - corr) * inv_nm1;
                    float w = (ta == tb) ? ((col > row) ? 2.f : (col == row ? 1.f : 0.f)) : 2.f;
                    local += w * fabsf(cd);
                }
        }

    __syncthreads();
    red[tid] = local;
    __syncthreads();
    for (int o = 128; o; o >>= 1) {
        if (tid < o) red[tid] += red[tid + o];
        __syncthreads();
    }
    if (tid == 0) atomicAdd(&g_cov[pair], red[0]);
}

// ---------------------------------------------------------------------------
// style: 128x64 CTA tile, 8 warps (4x2) of 32x32. sx in [0,512):
// lv = 3 - (sx>>7) (lv3 first), tile = sx & 127 -> i0 = (tile>>4)*128,
// j0 = (tile&15)*64. K-stage 32 channels, 3-stage cp.async ring.
// ---------------------------------------------------------------------------
__device__ __forceinline__ void style_body(int sx, int b, unsigned* s_aux) {
    unsigned* rm = s_aux;          // [0..127]
    unsigned* cmS = s_aux + 128;   // [128..191]

    int lv = 3 - (sx >> 7);
    int tile = sx & 127;
    int c = 64 << lv;
    int off = OFFC[lv];
    int N = (lv == 3) ? 1024 : 1000;
    int i0 = (tile >> 4) * 128, j0 = (tile & 15) * 64;
    int tid = threadIdx.x, wid = tid >> 5, lane = tid & 31;
    int g = lane >> 2, t = lane & 3;
    int grp = lane >> 3;
    int wm = (wid >> 1) * 32, wn = (wid & 1) * 32;
    const __half* X = g_spm + (size_t)b * SCRPB + off;
    const __half* Y = g_spm + (size_t)(8 + b) * SCRPB + off;

    if (tid < 128) rm[tid] = 0xFF800000u;
    if (tid < 64) cmS[128 - 128 + tid + 0] = 0xFF800000u;  // cmS[tid]
    if (tid < 64) cmS[tid] = 0xFF800000u;

    float acc[2][4][4];
#pragma unroll
    for (int mt = 0; mt < 2; mt++)
#pragma unroll
        for (int nt = 0; nt < 4; nt++)
#pragma unroll
            for (int rr = 0; rr < 4; rr++) acc[mt][nt][rr] = 0.f;

    int nk = c >> 5;

#define STY_ISSUE(S) do {                                                      \
        int k0_ = (S) * 32;                                                    \
        __half* A_ = (__half*)(dsm + ((S) % 3) * SSTGB);                       \
        __half* B_ = A_ + 128 * PS;                                            \
        _Pragma("unroll")                                                      \
        for (int j = 0; j < 3; j++) {                                          \
            int e = tid + j * 256;                                             \
            if (e < 512) {                                                     \
                int row = e >> 2, ch = (e & 3) * 8;                            \
                cp16(&A_[row * PS + ch], &X[(size_t)(i0 + row) * c + k0_ + ch]); \
            } else {                                                           \
                int f = e - 512;                                               \
                int row = f >> 2, ch = (f & 3) * 8;                            \
                cp16(&B_[row * PS + ch], &Y[(size_t)(j0 + row) * c + k0_ + ch]); \
            }                                                                  \
        }                                                                      \
        cp_commit();                                                           \
    } while (0)

    STY_ISSUE(0);
    if (nk > 1) STY_ISSUE(1);
    for (int i = 0; i < nk; i++) {
        if (i + 1 < nk) cp_wait1(); else cp_wait0();
        __syncthreads();
        if (i + 2 < nk) STY_ISSUE(i + 2);

        const __half* As = (const __half*)(dsm + (i % 3) * SSTGB);
        const __half* Bs = As + 128 * PS;
        // batch all fragment loads for both k16 steps, then all HMMAs
        unsigned a[2][2][4], bb[2][4][2];
#pragma unroll
        for (int s2 = 0; s2 < 2; s2++) {
            int kb = s2 * 16;
#pragma unroll
            for (int mt = 0; mt < 2; mt++) {
                int ar = wm + mt * 16 + (lane & 15);
                ldsm4(a[s2][mt][0], a[s2][mt][1], a[s2][mt][2], a[s2][mt][3],
                      &As[ar * PS + kb + ((lane >> 4) << 3)]);
            }
#pragma unroll
            for (int pp = 0; pp < 2; pp++) {
                int br = wn + (2 * pp + (grp >> 1)) * 8 + (lane & 7);
                ldsm4(bb[s2][2 * pp][0], bb[s2][2 * pp][1],
                      bb[s2][2 * pp + 1][0], bb[s2][2 * pp + 1][1],
                      &Bs[br * PS + kb + ((grp & 1) << 3)]);
            }
        }
#pragma unroll
        for (int s2 = 0; s2 < 2; s2++)
#pragma unroll
            for (int mt = 0; mt < 2; mt++)
#pragma unroll
                for (int nt = 0; nt < 4; nt++)
                    hmma16(acc[mt][nt], a[s2][mt], bb[s2][nt]);
    }
#undef STY_ISSUE

    // epilogue
    int pair = b * 4 + lv;
    const float* nsqX = g_nsq + pair * 1024;
    const float* nsqY = g_nsq + (32 + pair) * 1024;
    float invx[2][2], invy[4][2];
    bool vi[2][2], vj[4][2];
#pragma unroll
    for (int mt = 0; mt < 2; mt++)
#pragma unroll
        for (int h = 0; h < 2; h++) {
            int i = i0 + wm + mt * 16 + g + h * 8;
            vi[mt][h] = (i < N);
            invx[mt][h] = 1.f / (sqrtf(nsqX[i]) + 1e-10f);
        }
#pragma unroll
    for (int nt = 0; nt < 4; nt++)
#pragma unroll
        for (int u = 0; u < 2; u++) {
            int j = j0 + wn + nt * 8 + 2 * t + u;
            vj[nt][u] = (j < N);
            invy[nt][u] = 1.f / (sqrtf(nsqY[j]) + 1e-10f);
        }

    float rmin[2][2], cmin[4][2];
#pragma unroll
    for (int a1 = 0; a1 < 2; a1++)
#pragma unroll
        for (int a2 = 0; a2 < 2; a2++) rmin[a1][a2] = INFINITY;
#pragma unroll
    for (int a1 = 0; a1 < 4; a1++)
#pragma unroll
        for (int a2 = 0; a2 < 2; a2++) cmin[a1][a2] = INFINITY;

#pragma unroll
    for (int mt = 0; mt < 2; mt++)
#pragma unroll
        for (int nt = 0; nt < 4; nt++)
#pragma unroll
            for (int h = 0; h < 2; h++)
#pragma unroll
                for (int u = 0; u < 2; u++) {
                    float d = 1.f - acc[mt][nt][h * 2 + u] * invx[mt][h] * invy[nt][u];
                    float dr = vj[nt][u] ? d : INFINITY;
                    rmin[mt][h] = fminf(rmin[mt][h], dr);
                    float dc = vi[mt][h] ? d : INFINITY;
                    cmin[nt][u] = fminf(cmin[nt][u], dc);
                }

#pragma unroll
    for (int mt = 0; mt < 2; mt++)
#pragma unroll
        for (int h = 0; h < 2; h++) {
            float v = rmin[mt][h];
            v = fminf(v, __shfl_xor_sync(0xFFFFFFFFu, v, 1));
            v = fminf(v, __shfl_xor_sync(0xFFFFFFFFu, v, 2));
            rmin[mt][h] = v;
        }
#pragma unroll
    for (int nt = 0; nt < 4; nt++)
#pragma unroll
        for (int u = 0; u < 2; u++) {
            float v = cmin[nt][u];
            v = fminf(v, __shfl_xor_sync(0xFFFFFFFFu, v, 4));
            v = fminf(v, __shfl_xor_sync(0xFFFFFFFFu, v, 8));
            v = fminf(v, __shfl_xor_sync(0xFFFFFFFFu, v, 16));
            cmin[nt][u] = v;
        }
    if (t == 0) {
#pragma unroll
        for (int mt = 0; mt < 2; mt++)
#pragma unroll
            for (int h = 0; h < 2; h++)
                atomicMin(&rm[wm + mt * 16 + g + h * 8], f2o(rmin[mt][h]));
    }
    if (g == 0) {
#pragma unroll
        for (int nt = 0; nt < 4; nt++)
#pragma unroll
            for (int u = 0; u < 2; u++)
                atomicMin(&cmS[wn + nt * 8 + 2 * t + u], f2o(cmin[nt][u]));
    }
    __syncthreads();
    if (tid < 128) {
        int i = i0 + tid; if (i < N) atomicMin(&g_rmin[pair * 1024 + i], rm[tid]);
    } else if (tid < 192) {
        int j = j0 + (tid - 128); if (j < N) atomicMin(&g_cmin[pair * 1024 + j], cmS[tid - 128]);
    }
}

__global__ void __launch_bounds__(256, 3)
k_main() {
    __shared__ __align__(16) unsigned s_aux[256];
    if (blockIdx.x < 50) cov_body(blockIdx.x, blockIdx.y, s_aux);
    else                 style_body(blockIdx.x - 50, blockIdx.y, s_aux);
}

// ---------------------------------------------------------------------------
__device__ float blk_reduce1024(float v, float* smr) {
    int lane = threadIdx.x & 31, w = threadIdx.x >> 5;
#pragma unroll
    for (int o = 16; o; o >>= 1) v += __shfl_xor_sync(0xFFFFFFFFu, v, o);
    if (lane == 0) smr[w] = v;
    __syncthreads();
    float r = 0.f;
    if (w == 0) {
        r = smr[lane];
#pragma unroll
        for (int o = 16; o; o >>= 1) r += __shfl_xor_sync(0xFFFFFFFFu, r, o);
    }
    __syncthreads();
    return r;
}

__global__ void k_pairloss() {
    __shared__ float smr[32];
    const int cs[4] = {64, 128, 256, 512};
    int pair = blockIdx.x;
    int lv = pair & 3;
    int c = cs[lv], N = (lv == 3) ? 1024 : 1000;
    int tid = threadIdx.x;
    float v1 = 0.f, v2 = 0.f, v3 = 0.f;
    if (tid < N) {
        v1 = o2f(g_rmin[pair * 1024 + tid]);
        v2 = o2f(g_cmin[pair * 1024 + tid]);
    }
    if (tid < c) v3 = fabsf(g_musum[pair * 512 + tid] - g_musum[(32 + pair) * 512 + tid]);
    float s1 = blk_reduce1024(v1, smr);
    float s2 = blk_reduce1024(v2, smr);
    float s3 = blk_reduce1024(v3, smr);
    if (tid == 0) {
        float Nf = (float)N;
        float style = fmaxf(s1 / Nf, s2 / Nf);
        float mud   = s3 / ((float)c * Nf);
        float cov   = g_cov[pair] / ((float)c * (float)c);
        g_pl[pair] = style + mud + cov;
    }
}

__global__ void k_out(float* __restrict__ out) {
    float v = g_pl[threadIdx.x];
#pragma unroll
    for (int o = 16; o; o >>= 1) v += __shfl_xor_sync(0xFFFFFFFFu, v, o);
    if (threadIdx.x == 0) out[0] = v / 8.f;
}

// ---------------------------------------------------------------------------
extern "C" void kernel_launch(void* const* d_in, const int* in_sizes, int n_in,
                              void* d_out, int out_size) {
    const float* tf[4] = {0, 0, 0, 0};
    const float* gf[4] = {0, 0, 0, 0};
    const int*   ix[3] = {0, 0, 0};

    const long long LSZ[4] = {8LL * 64 * 256 * 256, 8LL * 128 * 128 * 128,
                              8LL * 256 * 64 * 64,  8LL * 512 * 32 * 32};
    int n_idx = 0;
    for (int i = 0; i < n_in; i++) {
        long long sz = in_sizes[i];
        if (sz == 8LL * 1000) {
            if (n_idx < 3) ix[n_idx++] = (const int*)d_in[i];
            continue;
        }
        for (int lv = 0; lv < 4; lv++) {
            if (sz == LSZ[lv]) {
                if (!tf[lv]) tf[lv] = (const float*)d_in[i];
                else if (!gf[lv]) gf[lv] = (const float*)d_in[i];
                break;
            }
        }
    }
    float* out = (float*)d_out;

    cudaFuncSetAttribute(k_main, cudaFuncAttributeMaxDynamicSharedMemorySize, DSMB);

    // k_main stays the 4th launch (ncu capture window).
    k_init_a<<<128, 256>>>();
    k_init_b<<<256, 256>>>();
    k_gather2<<<3840, 256>>>(tf[0], gf[0], tf[1], gf[1], tf[2], gf[2], tf[3], gf[3],
                             ix[0], ix[1], ix[2]);
    k_main<<<dim3(562, 8), 256, DSMB>>>();
    k_pairloss<<<32, 1024>>>();
    k_out<<<1, 32>>>(out);
}

// round 12
// speedup vs baseline: 1.0114x; 1.0114x over previous
#include <cuda_runtime.h>
#include <cuda_fp16.h>
#include <math.h>

// ---------------------------------------------------------------------------
// MotionOptimalTransportLoss — GB300 sm_103a
// fp16 mma.sync m16n8k16 (tcgen05 unavailable: harness emits compute_103 PTX).
// k_main reverted to R7 config (best measured): style 128x128 CTA tiles,
// 64x32 warp tiles, 2 CTA/SM; cov 64x64 tiles. 3-stage cp.async ring.
// Launch count reduced to 4 (init merged; pairloss+out merged, single block).
// ---------------------------------------------------------------------------

#define NPAD 1024
#define SCRPB 983040   // (64+128+256+512)*1024

__device__ __half    g_scm[2u * 8u * SCRPB];   // channel-major [c][1024]
__device__ __half    g_spm[2u * 8u * SCRPB];   // point-major  [1024][c]
__device__ float     g_nsq[2 * 32 * 1024];
__device__ float     g_musum[2 * 32 * 512];
__device__ unsigned  g_rmin[32 * 1024];
__device__ unsigned  g_cmin[32 * 1024];
__device__ float     g_cov[32];

__constant__ int OFFC[4] = {0, 65536, 196608, 458752};

__device__ __forceinline__ unsigned f2o(float f) {
    unsigned u = __float_as_uint(f);
    return (u & 0x80000000u) ? ~u : (u | 0x80000000u);
}
__device__ __forceinline__ float o2f(unsigned u) {
    return __uint_as_float((u & 0x80000000u) ? (u ^ 0x80000000u) : ~u);
}
__device__ __forceinline__ void hmma16(float* d, const unsigned* a, const unsigned* b) {
    asm volatile(
        "mma.sync.aligned.m16n8k16.row.col.f32.f16.f16.f32 "
        "{%0,%1,%2,%3}, {%4,%5,%6,%7}, {%8,%9}, {%0,%1,%2,%3};\n"
        : "+f"(d[0]), "+f"(d[1]), "+f"(d[2]), "+f"(d[3])
        : "r"(a[0]), "r"(a[1]), "r"(a[2]), "r"(a[3]), "r"(b[0]), "r"(b[1]));
}
__device__ __forceinline__ void ldsm4(unsigned& r0, unsigned& r1, unsigned& r2,
                                      unsigned& r3, const void* p) {
    unsigned addr = (unsigned)__cvta_generic_to_shared(p);
    asm volatile("ldmatrix.sync.aligned.m8n8.x4.shared.b16 {%0,%1,%2,%3}, [%4];"
                 : "=r"(r0), "=r"(r1), "=r"(r2), "=r"(r3) : "r"(addr));
}
__device__ __forceinline__ void cp16(void* dst, const void* src) {
    unsigned d = (unsigned)__cvta_generic_to_shared(dst);
    asm volatile("cp.async.cg.shared.global [%0], [%1], 16;\n" :: "r"(d), "l"(src));
}
__device__ __forceinline__ void cp_commit() { asm volatile("cp.async.commit_group;\n"); }
__device__ __forceinline__ void cp_wait1()  { asm volatile("cp.async.wait_group 1;\n"); }
__device__ __forceinline__ void cp_wait0()  { asm volatile("cp.async.wait_group 0;\n"); }

// ---------------------------------------------------------------------------
__global__ void k_init() {
    int i = blockIdx.x * blockDim.x + threadIdx.x;
    if (i < 65536) g_nsq[i] = 0.f;
    if (i < 32768) {
        g_rmin[i] = 0xFF800000u;
        g_cmin[i] = 0xFF800000u;
        g_musum[i] = 0.f;
    }
    if (i < 32) g_cov[i] = 0.f;
}

// ---------------------------------------------------------------------------
// gather2: fused gather + nsq + channel sums + dual-layout write.
// ---------------------------------------------------------------------------
__global__ void k_gather2(const float* __restrict__ tf0, const float* __restrict__ gf0,
                          const float* __restrict__ tf1, const float* __restrict__ gf1,
                          const float* __restrict__ tf2, const float* __restrict__ gf2,
                          const float* __restrict__ tf3, const float* __restrict__ gf3,
                          const int* __restrict__ ix0, const int* __restrict__ ix1,
                          const int* __restrict__ ix2) {
    __shared__ __half tl[64][72];

    int gblk = blockIdx.x;
    int tb = gblk / 240;
    int t2 = tb >> 3, b = tb & 7;
    int r = gblk % 240;
    int lv = 0;
    { const int sz[4] = {16, 32, 64, 128};
      while (r >= sz[lv]) { r -= sz[lv]; lv++; } }
    int C = 64 << lv;
    int ch0 = (r >> 4) * 64, n0 = (r & 15) * 64;
    int hw = 65536 >> (2 * lv);
    int N = (lv == 3) ? 1024 : 1000;

    const float* feat; const int* idx;
    switch (lv) {
        case 0: feat = t2 ? gf0 : tf0; idx = ix0; break;
        case 1: feat = t2 ? gf1 : tf1; idx = ix1; break;
        case 2: feat = t2 ? gf2 : tf2; idx = ix2; break;
        default: feat = t2 ? gf3 : tf3; idx = 0; break;
    }

    int tid = threadIdx.x;
    int nl = tid & 63;
    int n = n0 + nl;
    int chg = tid >> 6;
    bool valid = (n < N);
    int src = 0;
    if (valid) src = idx ? idx[b * 1000 + n] : n;

    size_t fb = ((size_t)b * C + ch0) * hw + src;
    __half* cm = g_scm + ((size_t)t2 * 8 + b) * SCRPB + OFFC[lv];
    float nsq_loc = 0.f;
#pragma unroll
    for (int k = 0; k < 16; k++) {
        int chl = chg * 16 + k;
        float v = valid ? feat[fb + (size_t)chl * hw] : 0.f;
        nsq_loc += v * v;
        __half h = __float2half_rn(v);
        cm[(size_t)(ch0 + chl) * NPAD + n] = h;
        tl[chl][nl] = h;
    }
    int pairbase = (t2 * 32 + b * 4 + lv) * 1024;
    atomicAdd(&g_nsq[pairbase + n], nsq_loc);
    __syncthreads();

    __half* pm = g_spm + ((size_t)t2 * 8 + b) * SCRPB + OFFC[lv];
    int row = tid >> 2, q = tid & 3;
#pragma unroll
    for (int j = 0; j < 8; j++) {
        int cc = q * 16 + 2 * j;
        __half2 w = __halves2half2(tl[cc][row], tl[cc + 1][row]);
        *(__half2*)&pm[(size_t)(n0 + row) * C + ch0 + cc] = w;
    }

    {
        int ch = tid >> 2;
        float s = 0.f;
#pragma unroll
        for (int i2 = 0; i2 < 16; i2++) s += __half2float(tl[ch][q * 16 + i2]);
        s += __shfl_xor_sync(0xFFFFFFFFu, s, 1);
        s += __shfl_xor_sync(0xFFFFFFFFu, s, 2);
        if (q == 0)
            atomicAdd(&g_musum[(t2 * 32 + b * 4 + lv) * 512 + ch0 + ch], s);
    }
}

// ---------------------------------------------------------------------------
// k_main: merged cov + style (R7 config). grid (306, 8).
// ---------------------------------------------------------------------------
#define PS 40                      // style smem row stride (halves)
#define SSTGB (2 * 128 * PS * 2)   // 20480 B per style stage (A + B)
#define CS 72                      // cov smem row stride (halves)
#define CSTGB (2 * 64 * CS * 2)    // 18432 B per cov stage
#define DSMB (3 * SSTGB)           // 61440

extern __shared__ char dsm[];

__device__ __forceinline__ void cov_body(int bx, int b, unsigned* s_aux) {
    float* red = (float*)s_aux;
    int lv = 0;
    { const int TRI[4] = {1, 3, 10, 36};
      while (bx >= TRI[lv]) { bx -= TRI[lv]; lv++; } }
    int T = 1 << lv;
    int ta = 0, rem = bx;
    while (rem >= T - ta) { rem -= (T - ta); ta++; }
    int tb = ta + rem;

    int off = OFFC[lv];
    int N = (lv == 3) ? 1024 : 1000;
    int tid = threadIdx.x, wid = tid >> 5, lane = tid & 31;
    int g = lane >> 2, t = lane & 3;
    int grp = lane >> 3;
    int wm = (wid >> 2) * 32, wn = (wid & 3) * 16;
    int cha0 = ta * 64, chb0 = tb * 64;
    const __half* X = g_scm + (size_t)b * SCRPB + off;
    const __half* Y = g_scm + (size_t)(8 + b) * SCRPB + off;

    float acc[2][2][2][4];
#pragma unroll
    for (int p = 0; p < 2; p++)
#pragma unroll
        for (int mt = 0; mt < 2; mt++)
#pragma unroll
            for (int nt = 0; nt < 2; nt++)
#pragma unroll
                for (int rr = 0; rr < 4; rr++) acc[p][mt][nt][rr] = 0.f;

    int lrow = tid >> 2, lq = tid & 3;

#define COV_ISSUE(IT) do {                                                     \
        int p_ = (IT) >> 4, n1_ = ((IT) & 15) * 64;                            \
        const __half* s_ = p_ ? Y : X;                                         \
        __half* A_ = (__half*)(dsm + ((IT) % 3) * CSTGB);                      \
        __half* B_ = A_ + 64 * CS;                                             \
        _Pragma("unroll")                                                      \
        for (int j = 0; j < 2; j++) {                                          \
            int col = lq * 16 + j * 8;                                         \
            cp16(&A_[lrow * CS + col], &s_[(size_t)(cha0 + lrow) * NPAD + n1_ + col]); \
            cp16(&B_[lrow * CS + col], &s_[(size_t)(chb0 + lrow) * NPAD + n1_ + col]); \
        }                                                                      \
        cp_commit();                                                           \
    } while (0)

    COV_ISSUE(0);
    COV_ISSUE(1);
    for (int it = 0; it < 32; it++) {
        if (it + 1 < 32) cp_wait1(); else cp_wait0();
        __syncthreads();
        if (it + 2 < 32) COV_ISSUE(it + 2);

        int p = it >> 4;
        const __half* As = (const __half*)(dsm + (it % 3) * CSTGB);
        const __half* Bsm = As + 64 * CS;
#pragma unroll
        for (int k16 = 0; k16 < 64; k16 += 16) {
            unsigned a[2][4], bb[2][2];
#pragma unroll
            for (int mt = 0; mt < 2; mt++) {
                int ar = wm + mt * 16 + (lane & 15);
                ldsm4(a[mt][0], a[mt][1], a[mt][2], a[mt][3],
                      &As[ar * CS + k16 + ((lane >> 4) << 3)]);
            }
            {
                int br = wn + (grp >> 1) * 8 + (lane & 7);
                ldsm4(bb[0][0], bb[0][1], bb[1][0], bb[1][1],
                      &Bsm[br * CS + k16 + ((grp & 1) << 3)]);
            }
#pragma unroll
            for (int mt = 0; mt < 2; mt++)
#pragma unroll
                for (int nt = 0; nt < 2; nt++) hmma16(acc[p][mt][nt], a[mt], bb[nt]);
        }
    }
#undef COV_ISSUE

    int pair = b * 4 + lv;
    const float* sux = g_musum + pair * 512;
    const float* suy = g_musum + (32 + pair) * 512;
    float Nf = (float)N, inv_nm1 = 1.f / (Nf - 1.f), invN = 1.f / Nf;
    float local = 0.f;
#pragma unroll
    for (int mt = 0; mt < 2; mt++)
#pragma unroll
        for (int h = 0; h < 2; h++) {
            int row = cha0 + wm + mt * 16 + g + h * 8;
            float sxa = sux[row], sya = suy[row];
#pragma unroll
            for (int nt = 0; nt < 2; nt++)
#pragma unroll
                for (int u = 0; u < 2; u++) {
                    int col = chb0 + wn + nt * 8 + 2 * t + u;
                    float corr = (sxa * sux[col] - sya * suy[col]) * invN;
                    float cd = (acc[0][mt][nt][h * 2 + u] - acc[1][mt][nt][h * 2 + u]
                                - corr) * inv_nm1;
                    float w = (ta == tb) ? ((col > row) ? 2.f : (col == row ? 1.f : 0.f)) : 2.f;
                    local += w * fabsf(cd);
                }
        }

    __syncthreads();
    red[tid] = local;
    __syncthreads();
    for (int o = 128; o; o >>= 1) {
        if (tid < o) red[tid] += red[tid + o];
        __syncthreads();
    }
    if (tid == 0) atomicAdd(&g_cov[pair], red[0]);
}

__device__ __forceinline__ void style_body(int sx, int b, unsigned* s_aux) {
    unsigned* rm = s_aux;
    unsigned* cmS = s_aux + 128;

    int lv = 3 - (sx >> 6);
    int tile = sx & 63;
    int c = 64 << lv;
    int off = OFFC[lv];
    int N = (lv == 3) ? 1024 : 1000;
    int i0 = (tile >> 3) * 128, j0 = (tile & 7) * 128;
    int tid = threadIdx.x, wid = tid >> 5, lane = tid & 31;
    int g = lane >> 2, t = lane & 3;
    int grp = lane >> 3;
    int wm = (wid >> 2) * 64, wn = (wid & 3) * 32;
    const __half* X = g_spm + (size_t)b * SCRPB + off;
    const __half* Y = g_spm + (size_t)(8 + b) * SCRPB + off;

    if (tid < 128) { rm[tid] = 0xFF800000u; cmS[tid] = 0xFF800000u; }

    float acc[4][4][4];
#pragma unroll
    for (int mt = 0; mt < 4; mt++)
#pragma unroll
        for (int nt = 0; nt < 4; nt++)
#pragma unroll
            for (int rr = 0; rr < 4; rr++) acc[mt][nt][rr] = 0.f;

    int lrow = tid >> 1, lq = tid & 1;
    int nk = c >> 5;

#define STY_ISSUE(S) do {                                                      \
        int k0_ = (S) * 32;                                                    \
        __half* A_ = (__half*)(dsm + ((S) % 3) * SSTGB);                       \
        __half* B_ = A_ + 128 * PS;                                            \
        _Pragma("unroll")                                                      \
        for (int j = 0; j < 2; j++) {                                          \
            int col = lq * 16 + j * 8;                                         \
            cp16(&A_[lrow * PS + col], &X[(size_t)(i0 + lrow) * c + k0_ + col]); \
            cp16(&B_[lrow * PS + col], &Y[(size_t)(j0 + lrow) * c + k0_ + col]); \
        }                                                                      \
        cp_commit();                                                           \
    } while (0)

    STY_ISSUE(0);
    if (nk > 1) STY_ISSUE(1);
    for (int i = 0; i < nk; i++) {
        if (i + 1 < nk) cp_wait1(); else cp_wait0();
        __syncthreads();
        if (i + 2 < nk) STY_ISSUE(i + 2);

        const __half* As = (const __half*)(dsm + (i % 3) * SSTGB);
        const __half* Bs = As + 128 * PS;
#pragma unroll
        for (int kb = 0; kb < 32; kb += 16) {
            unsigned a[4][4], bb[4][2];
#pragma unroll
            for (int mt = 0; mt < 4; mt++) {
                int ar = wm + mt * 16 + (lane & 15);
                ldsm4(a[mt][0], a[mt][1], a[mt][2], a[mt][3],
                      &As[ar * PS + kb + ((lane >> 4) << 3)]);
            }
#pragma unroll
            for (int pp = 0; pp < 2; pp++) {
                int br = wn + (2 * pp + (grp >> 1)) * 8 + (lane & 7);
                ldsm4(bb[2 * pp][0], bb[2 * pp][1], bb[2 * pp + 1][0], bb[2 * pp + 1][1],
                      &Bs[br * PS + kb + ((grp & 1) << 3)]);
            }
#pragma unroll
            for (int mt = 0; mt < 4; mt++)
#pragma unroll
                for (int nt = 0; nt < 4; nt++) hmma16(acc[mt][nt], a[mt], bb[nt]);
        }
    }
#undef STY_ISSUE

    int pair = b * 4 + lv;
    const float* nsqX = g_nsq + pair * 1024;
    const float* nsqY = g_nsq + (32 + pair) * 1024;
    float invx[4][2], invy[4][2];
    bool vi[4][2], vj[4][2];
#pragma unroll
    for (int mt = 0; mt < 4; mt++)
#pragma unroll
        for (int h = 0; h < 2; h++) {
            int i = i0 + wm + mt * 16 + g + h * 8;
            vi[mt][h] = (i < N);
            invx[mt][h] = 1.f / (sqrtf(nsqX[i]) + 1e-10f);
        }
#pragma unroll
    for (int nt = 0; nt < 4; nt++)
#pragma unroll
        for (int u = 0; u < 2; u++) {
            int j = j0 + wn + nt * 8 + 2 * t + u;
            vj[nt][u] = (j < N);
            invy[nt][u] = 1.f / (sqrtf(nsqY[j]) + 1e-10f);
        }

    float rmin[4][2], cmin[4][2];
#pragma unroll
    for (int a1 = 0; a1 < 4; a1++)
#pragma unroll
        for (int a2 = 0; a2 < 2; a2++) { rmin[a1][a2] = INFINITY; cmin[a1][a2] = INFINITY; }

#pragma unroll
    for (int mt = 0; mt < 4; mt++)
#pragma unroll
        for (int nt = 0; nt < 4; nt++)
#pragma unroll
            for (int h = 0; h < 2; h++)
#pragma unroll
                for (int u = 0; u < 2; u++) {
                    float d = 1.f - acc[mt][nt][h * 2 + u] * invx[mt][h] * invy[nt][u];
                    float dr = vj[nt][u] ? d : INFINITY;
                    rmin[mt][h] = fminf(rmin[mt][h], dr);
                    float dc = vi[mt][h] ? d : INFINITY;
                    cmin[nt][u] = fminf(cmin[nt][u], dc);
                }

#pragma unroll
    for (int mt = 0; mt < 4; mt++)
#pragma unroll
        for (int h = 0; h < 2; h++) {
            float v = rmin[mt][h];
            v = fminf(v, __shfl_xor_sync(0xFFFFFFFFu, v, 1));
            v = fminf(v, __shfl_xor_sync(0xFFFFFFFFu, v, 2));
            rmin[mt][h] = v;
        }
#pragma unroll
    for (int nt = 0; nt < 4; nt++)
#pragma unroll
        for (int u = 0; u < 2; u++) {
            float v = cmin[nt][u];
            v = fminf(v, __shfl_xor_sync(0xFFFFFFFFu, v, 4));
            v = fminf(v, __shfl_xor_sync(0xFFFFFFFFu, v, 8));
            v = fminf(v, __shfl_xor_sync(0xFFFFFFFFu, v, 16));
            cmin[nt][u] = v;
        }
    if (t == 0) {
#pragma unroll
        for (int mt = 0; mt < 4; mt++)
#pragma unroll
            for (int h = 0; h < 2; h++)
                atomicMin(&rm[wm + mt * 16 + g + h * 8], f2o(rmin[mt][h]));
    }
    if (g == 0) {
#pragma unroll
        for (int nt = 0; nt < 4; nt++)
#pragma unroll
            for (int u = 0; u < 2; u++)
                atomicMin(&cmS[wn + nt * 8 + 2 * t + u], f2o(cmin[nt][u]));
    }
    __syncthreads();
    if (tid < 128) {
        int i = i0 + tid; if (i < N) atomicMin(&g_rmin[pair * 1024 + i], rm[tid]);
        int j = j0 + tid; if (j < N) atomicMin(&g_cmin[pair * 1024 + j], cmS[tid]);
    }
}

__global__ void __launch_bounds__(256, 2)
k_main() {
    __shared__ __align__(16) unsigned s_aux[256];
    if (blockIdx.x < 50) cov_body(blockIdx.x, blockIdx.y, s_aux);
    else                 style_body(blockIdx.x - 50, blockIdx.y, s_aux);
}

// ---------------------------------------------------------------------------
// k_fin: fused pairloss + final mean. Single block, 1024 threads.
// Warp w handles pair w (32 pairs). Lane-strided reductions over 1024 points.
// ---------------------------------------------------------------------------
__global__ void k_fin(float* __restrict__ out) {
    __shared__ float pl[32];
    int wid = threadIdx.x >> 5, lane = threadIdx.x & 31;
    int pair = wid;
    int lv = pair & 3;
    int c = 64 << lv;
    int N = (lv == 3) ? 1024 : 1000;

    float s1 = 0.f, s2 = 0.f, s3 = 0.f;
    const unsigned* rp = g_rmin + pair * 1024;
    const unsigned* cp = g_cmin + pair * 1024;
#pragma unroll
    for (int q = 0; q < 32; q++) {
        int n = q * 32 + lane;
        if (n < N) {
            s1 += o2f(rp[n]);
            s2 += o2f(cp[n]);
        }
    }
    const float* mx = g_musum + pair * 512;
    const float* my = g_musum + (32 + pair) * 512;
    for (int ch = lane; ch < c; ch += 32) s3 += fabsf(mx[ch] - my[ch]);

#pragma unroll
    for (int o = 16; o; o >>= 1) {
        s1 += __shfl_xor_sync(0xFFFFFFFFu, s1, o);
        s2 += __shfl_xor_sync(0xFFFFFFFFu, s2, o);
        s3 += __shfl_xor_sync(0xFFFFFFFFu, s3, o);
    }
    if (lane == 0) {
        float Nf = (float)N;
        float style = fmaxf(s1 / Nf, s2 / Nf);
        float mud   = s3 / ((float)c * Nf);
        float cov   = g_cov[pair] / ((float)c * (float)c);
        pl[pair] = style + mud + cov;
    }
    __syncthreads();
    if (wid == 0) {
        float v = pl[lane];
#pragma unroll
        for (int o = 16; o; o >>= 1) v += __shfl_xor_sync(0xFFFFFFFFu, v, o);
        if (lane == 0) out[0] = v / 8.f;
    }
}

// ---------------------------------------------------------------------------
extern "C" void kernel_launch(void* const* d_in, const int* in_sizes, int n_in,
                              void* d_out, int out_size) {
    const float* tf[4] = {0, 0, 0, 0};
    const float* gf[4] = {0, 0, 0, 0};
    const int*   ix[3] = {0, 0, 0};

    const long long LSZ[4] = {8LL * 64 * 256 * 256, 8LL * 128 * 128 * 128,
                              8LL * 256 * 64 * 64,  8LL * 512 * 32 * 32};
    int n_idx = 0;
    for (int i = 0; i < n_in; i++) {
        long long sz = in_sizes[i];
        if (sz == 8LL * 1000) {
            if (n_idx < 3) ix[n_idx++] = (const int*)d_in[i];
            continue;
        }
        for (int lv = 0; lv < 4; lv++) {
            if (sz == LSZ[lv]) {
                if (!tf[lv]) tf[lv] = (const float*)d_in[i];
                else if (!gf[lv]) gf[lv] = (const float*)d_in[i];
                break;
            }
        }
    }
    float* out = (float*)d_out;

    cudaFuncSetAttribute(k_main, cudaFuncAttributeMaxDynamicSharedMemorySize, DSMB);

    k_init<<<256, 256>>>();
    k_gather2<<<3840, 256>>>(tf[0], gf[0], tf[1], gf[1], tf[2], gf[2], tf[3], gf[3],
                             ix[0], ix[1], ix[2]);
    k_main<<<dim3(306, 8), 256, DSMB>>>();
    k_fin<<<1, 1024>>>(out);
}